// round 3
// baseline (speedup 1.0000x reference)
#include <cuda_runtime.h>
#include <cstdint>

// ---------------------------------------------------------------------------
// LSTM: T=512, B=64, IN=512, H=1024.
// Phase 1 (parallel): Gx = X @ Wx + b for all t (one big GEMM into g_gx).
// Phase 2: persistent kernel, 128 blocks (1/SM). Block bx owns 8 H-cols x 4
// gates = 32 output columns. Weight slice (128KB) resident in SMEM.
// Step GEMM thread map: lane = column (32 lanes = whole block N), warp = 8
// batch rows -> As reads are warp-broadcast (crossbar-free), W reads are the
// only distinct LDS traffic. fma2-pipe-bound by design.
// ---------------------------------------------------------------------------

static constexpr int kT  = 512;
static constexpr int kB  = 64;
static constexpr int kIN = 512;
static constexpr int kH  = 1024;
static constexpr int kGXW = 4 * kH;          // 4096
static constexpr int kBH = kB * kH;          // 65536
static constexpr int NBLK = 128;

typedef unsigned long long ull;

__device__ float g_gx[(size_t)kT * kB * kGXW];   // 512 MB scratch
__device__ unsigned g_bar;

__device__ __forceinline__ void fma2(ull& d, ull a, ull b) {
    asm("fma.rn.f32x2 %0, %1, %2, %0;" : "+l"(d) : "l"(a), "l"(b));
}
__device__ __forceinline__ float redpair(ull v) {
    float2 f = *reinterpret_cast<float2*>(&v);
    return f.x + f.y;
}
__device__ __forceinline__ float sigmoidf_(float x) {
    return 1.0f / (1.0f + __expf(-x));
}

__global__ void reset_kernel() { g_bar = 0u; }

// ---------------------------------------------------------------------------
// Phase 1: Gx = X @ Wx + b.  (unchanged from R2)
// ---------------------------------------------------------------------------
static constexpr int P1_BM = 128;
static constexpr int P1_BN = 64;
static constexpr int P1_BK = 32;

__global__ void __launch_bounds__(256) phase1_kernel(
    const float* __restrict__ x,
    const float* __restrict__ Wf, const float* __restrict__ Wi,
    const float* __restrict__ Wc, const float* __restrict__ Wo,
    const float* __restrict__ bf, const float* __restrict__ bi,
    const float* __restrict__ bc, const float* __restrict__ bo)
{
    __shared__ float As[P1_BM][P1_BK + 4];
    __shared__ float Bsm[P1_BK / 2][P1_BN * 2];

    const int tid  = threadIdx.x;
    const int gate = blockIdx.x >> 4;
    const int n0   = (blockIdx.x & 15) * P1_BN;
    const int m0   = blockIdx.y * P1_BM;

    const float* W    = (gate == 0) ? Wf : (gate == 1) ? Wi : (gate == 2) ? Wc : Wo;
    const float* bias = (gate == 0) ? bf : (gate == 1) ? bi : (gate == 2) ? bc : bo;

    const int ng = tid & 7;
    const int mg = tid >> 3;

    ull acc[4][8];
#pragma unroll
    for (int i = 0; i < 4; i++)
#pragma unroll
        for (int j = 0; j < 8; j++) acc[i][j] = 0ull;

    float4 pa[4];
    float4 pb0, pb1;
    {
#pragma unroll
        for (int r = 0; r < 4; r++) {
            int idx = tid + r * 256;
            int m = idx >> 3, fk = idx & 7;
            pa[r] = *reinterpret_cast<const float4*>(&x[(size_t)(m0 + m) * kIN + 4 * fk]);
        }
        int kk = tid >> 3, fn = tid & 7;
        const float* wr = &W[(size_t)(kH + kk) * kH + n0 + 8 * fn];
        pb0 = *reinterpret_cast<const float4*>(wr);
        pb1 = *reinterpret_cast<const float4*>(wr + 4);
    }

    const int NCH = kIN / P1_BK;
    for (int c = 0; c < NCH; ++c) {
        __syncthreads();
#pragma unroll
        for (int r = 0; r < 4; r++) {
            int idx = tid + r * 256;
            int m = idx >> 3, fk = idx & 7;
            *reinterpret_cast<float4*>(&As[m][4 * fk]) = pa[r];
        }
        {
            int kk = tid >> 3, fn = tid & 7;
            float* brow = &Bsm[kk >> 1][0];
            int half = kk & 1;
            int vb = 8 * fn;
            brow[(vb + 0) * 2 + half] = pb0.x;
            brow[(vb + 1) * 2 + half] = pb0.y;
            brow[(vb + 2) * 2 + half] = pb0.z;
            brow[(vb + 3) * 2 + half] = pb0.w;
            brow[(vb + 4) * 2 + half] = pb1.x;
            brow[(vb + 5) * 2 + half] = pb1.y;
            brow[(vb + 6) * 2 + half] = pb1.z;
            brow[(vb + 7) * 2 + half] = pb1.w;
        }
        __syncthreads();
        if (c + 1 < NCH) {
            int kc = (c + 1) * P1_BK;
#pragma unroll
            for (int r = 0; r < 4; r++) {
                int idx = tid + r * 256;
                int m = idx >> 3, fk = idx & 7;
                pa[r] = *reinterpret_cast<const float4*>(&x[(size_t)(m0 + m) * kIN + kc + 4 * fk]);
            }
            int kk = tid >> 3, fn = tid & 7;
            const float* wr = &W[(size_t)(kH + kc + kk) * kH + n0 + 8 * fn];
            pb0 = *reinterpret_cast<const float4*>(wr);
            pb1 = *reinterpret_cast<const float4*>(wr + 4);
        }
#pragma unroll
        for (int k2 = 0; k2 < P1_BK / 2; ++k2) {
            ull a[4];
#pragma unroll
            for (int i = 0; i < 4; i++)
                a[i] = *reinterpret_cast<const ull*>(&As[4 * mg + i][2 * k2]);
            ull b[8];
#pragma unroll
            for (int s = 0; s < 4; s++) {
                float4 q = *reinterpret_cast<const float4*>(&Bsm[k2][16 * ng + 4 * s]);
                b[2 * s + 0] = reinterpret_cast<ull*>(&q)[0];
                b[2 * s + 1] = reinterpret_cast<ull*>(&q)[1];
            }
#pragma unroll
            for (int i = 0; i < 4; i++)
#pragma unroll
                for (int j = 0; j < 8; j++)
                    fma2(acc[i][j], a[i], b[j]);
        }
    }

    float4 bb0 = *reinterpret_cast<const float4*>(&bias[n0 + 8 * ng]);
    float4 bb1 = *reinterpret_cast<const float4*>(&bias[n0 + 8 * ng + 4]);
#pragma unroll
    for (int i = 0; i < 4; i++) {
        int m = m0 + 4 * mg + i;
        float* orow = &g_gx[(size_t)m * kGXW + gate * kH + n0 + 8 * ng];
        float4 o0, o1;
        o0.x = redpair(acc[i][0]) + bb0.x;
        o0.y = redpair(acc[i][1]) + bb0.y;
        o0.z = redpair(acc[i][2]) + bb0.z;
        o0.w = redpair(acc[i][3]) + bb0.w;
        o1.x = redpair(acc[i][4]) + bb1.x;
        o1.y = redpair(acc[i][5]) + bb1.y;
        o1.z = redpair(acc[i][6]) + bb1.z;
        o1.w = redpair(acc[i][7]) + bb1.w;
        *reinterpret_cast<float4*>(orow) = o0;
        *reinterpret_cast<float4*>(orow + 4) = o1;
    }
}

// ---------------------------------------------------------------------------
// Persistent phase-2 kernel. 128 blocks x 256 threads, 1 block/SM.
// SMEM: Wres [512 k2][32 vn] ull (128KB) + As double buffer + pre + c.
// ---------------------------------------------------------------------------
static constexpr int S_CH = 64;          // K-chunk (floats)
static constexpr int S_NCH = kH / S_CH;  // 16 chunks
static constexpr int S_RS = S_CH + 4;    // As row stride (68 floats)
static constexpr int SM_W   = 512 * 64;             // 32768 floats (ull view: 512x32)
static constexpr int SM_AS  = 2 * kB * S_RS;        // 8704
static constexpr int SM_PRE = kB * 32;               // 2048
static constexpr int SM_C   = kB * 8;                // 512
static constexpr int SM_BYTES = (SM_W + SM_AS + SM_PRE + SM_C) * 4;   // 176128

__global__ void __launch_bounds__(256, 1) lstm_persistent(
    float* __restrict__ out,
    const float* __restrict__ Wf, const float* __restrict__ Wi,
    const float* __restrict__ Wc, const float* __restrict__ Wo)
{
    extern __shared__ float sm[];
    float* Wres_f = sm;                  // [k2][vn*2+half]
    float* As     = sm + SM_W;           // 2 x [64][S_RS]
    float* pre_s  = As + SM_AS;          // [64][32]
    float* c_s    = pre_s + SM_PRE;      // [64][8]
    const ull* Wres = reinterpret_cast<const ull*>(Wres_f);

    const int tid  = threadIdx.x;
    const int bx   = blockIdx.x;
    const int n0h  = bx * 8;
    const int lane = tid & 31;   // vn = gate*8 + col
    const int wrp  = tid >> 5;   // rows 8*wrp .. 8*wrp+7

    // resident weight slice: Wres[k2*32 + vn] = (W[2k2][n], W[2k2+1][n])
    for (int g = 0; g < 4; g++) {
        const float* W = (g == 0) ? Wf : (g == 1) ? Wi : (g == 2) ? Wc : Wo;
        for (int idx = tid; idx < kH * 8; idx += 256) {
            int r = idx >> 3, col = idx & 7;
            Wres_f[(r >> 1) * 64 + (g * 8 + col) * 2 + (r & 1)] =
                W[(size_t)r * kH + n0h + col];
        }
    }
    for (int i = tid; i < SM_C; i += 256) c_s[i] = 0.0f;
    __syncthreads();

    const int gate_ = lane >> 3;
    const int col_  = lane & 7;

    for (int t = 0; t < kT; ++t) {
        // Gx contributions for this thread's 8 (row, vn) outputs
        float gxv[8];
        {
            const float* gx = g_gx + (size_t)t * kB * kGXW + gate_ * kH + n0h + col_;
#pragma unroll
            for (int i = 0; i < 8; i++)
                gxv[i] = gx[(size_t)(8 * wrp + i) * kGXW];
        }

        float pre[8];
        if (t == 0) {
#pragma unroll
            for (int i = 0; i < 8; i++) pre[i] = gxv[i];
        } else {
            const float* hprev = out + (size_t)(t - 1) * kBH;
            ull acc[8];
#pragma unroll
            for (int i = 0; i < 8; i++) acc[i] = 0ull;

            float4 pa[4];
#pragma unroll
            for (int r = 0; r < 4; r++) {
                int idx = tid + r * 256;
                int row = idx >> 4, f4 = idx & 15;
                pa[r] = *reinterpret_cast<const float4*>(&hprev[(size_t)row * kH + 4 * f4]);
            }

            for (int c = 0; c < S_NCH; ++c) {
                float* buf = As + (c & 1) * kB * S_RS;
#pragma unroll
                for (int r = 0; r < 4; r++) {
                    int idx = tid + r * 256;
                    int row = idx >> 4, f4 = idx & 15;
                    *reinterpret_cast<float4*>(&buf[row * S_RS + 4 * f4]) = pa[r];
                }
                __syncthreads();
                if (c + 1 < S_NCH) {
                    int kc = (c + 1) * S_CH;
#pragma unroll
                    for (int r = 0; r < 4; r++) {
                        int idx = tid + r * 256;
                        int row = idx >> 4, f4 = idx & 15;
                        pa[r] = *reinterpret_cast<const float4*>(
                            &hprev[(size_t)row * kH + kc + 4 * f4]);
                    }
                }
                const ull* wrow = Wres + (size_t)(c * 32) * 32 + lane;
                const float* arow = buf + (8 * wrp) * S_RS;
#pragma unroll
                for (int kk = 0; kk < 16; ++kk) {
                    ull w0 = wrow[(2 * kk) * 32];
                    ull w1 = wrow[(2 * kk + 1) * 32];
#pragma unroll
                    for (int i = 0; i < 8; i++) {
                        float4 a4 = *reinterpret_cast<const float4*>(
                            &arow[i * S_RS + 4 * kk]);
                        ull a0 = reinterpret_cast<ull*>(&a4)[0];
                        ull a1 = reinterpret_cast<ull*>(&a4)[1];
                        fma2(acc[i], a0, w0);
                        fma2(acc[i], a1, w1);
                    }
                }
            }
#pragma unroll
            for (int i = 0; i < 8; i++) pre[i] = redpair(acc[i]) + gxv[i];
        }

        // publish pre-activations (lane-contiguous rows: conflict-free)
#pragma unroll
        for (int i = 0; i < 8; i++)
            pre_s[(8 * wrp + i) * 32 + lane] = pre[i];
        __syncthreads();

        // gate math + c/h update (block owns 64b x 8 cols)
#pragma unroll
        for (int r = 0; r < 2; r++) {
            int idx = tid + r * 256;
            int b = idx >> 3, j = idx & 7;
            float f  = sigmoidf_(pre_s[b * 32 + j]);
            float ii = sigmoidf_(pre_s[b * 32 + 8 + j]);
            float gg = tanhf(pre_s[b * 32 + 16 + j]);
            float oo = sigmoidf_(pre_s[b * 32 + 24 + j]);
            float cn = f * c_s[b * 8 + j] + ii * gg;
            c_s[b * 8 + j] = cn;
            float h = oo * tanhf(cn);
            out[(size_t)t * kBH + (size_t)b * kH + n0h + j] = h;
            if (t == kT - 1) {
                out[(size_t)kT * kBH + (size_t)b * kH + n0h + j] = h;
                out[(size_t)kT * kBH + kBH + (size_t)b * kH + n0h + j] = cn;
            }
        }

        // global barrier between steps
        if (t < kT - 1) {
            __threadfence();
            __syncthreads();
            if (tid == 0) {
                atomicAdd(&g_bar, 1u);
                unsigned target = (unsigned)(t + 1) * NBLK;
                while (*((volatile unsigned*)&g_bar) < target) { __nanosleep(32); }
            }
            __syncthreads();
        }
    }
}

// ---------------------------------------------------------------------------
extern "C" void kernel_launch(void* const* d_in, const int* in_sizes, int n_in,
                              void* d_out, int out_size)
{
    const float* x  = (const float*)d_in[0];
    const float* Wf = (const float*)d_in[1];
    const float* bf = (const float*)d_in[2];
    const float* Wi = (const float*)d_in[3];
    const float* bi = (const float*)d_in[4];
    const float* Wc = (const float*)d_in[5];
    const float* bc = (const float*)d_in[6];
    const float* Wo = (const float*)d_in[7];
    const float* bo = (const float*)d_in[8];
    float* out = (float*)d_out;

    cudaFuncSetAttribute(lstm_persistent,
                         cudaFuncAttributeMaxDynamicSharedMemorySize, SM_BYTES);

    reset_kernel<<<1, 1>>>();

    dim3 g1(64, kT * kB / P1_BM);
    phase1_kernel<<<g1, 256>>>(x, Wf, Wi, Wc, Wo, bf, bi, bc, bo);

    lstm_persistent<<<NBLK, 256, SM_BYTES>>>(out, Wf, Wi, Wc, Wo);
}

// round 5
// speedup vs baseline: 1.3125x; 1.3125x over previous
#include <cuda_runtime.h>
#include <cuda_bf16.h>
#include <cstdint>

// ---------------------------------------------------------------------------
// LSTM T=512, B=64, IN=512, H=1024.
// Phase 1 (scalar fp32 GEMM, exact): gx[t][cta][b][vn] = x_t @ Wx + bias.
// Phase 2 (persistent, 128 CTAs): recurrent GEMM h@Wh on warp-level
//   mma.sync.m16n8k16 bf16 (HMMA) with 3-term hi/lo split, fp32 accum.
//   CTA owns 32 output cols (4 gates x 8 H-cols); W slice resident in SMEM.
//   h chain: bf16 hi/lo global buffers; c state in SMEM; steps separated by
//   a global arrive+spin barrier. No tcgen05 (not supported by this build).
// ---------------------------------------------------------------------------

static constexpr int kT  = 512;
static constexpr int kB  = 64;
static constexpr int kIN = 512;
static constexpr int kH  = 1024;
static constexpr int kBH = kB * kH;
static constexpr int NBLK = 128;

typedef unsigned long long ull;

// ---- device globals (allocation-free scratch) ----
__device__ float g_gx2[(size_t)kT * NBLK * kB * 32];      // [t][cta][b][vn]
__device__ __nv_bfloat16 g_whi2[(size_t)NBLK * 32768];    // per-CTA W hi [n=32][k=1024]
__device__ __nv_bfloat16 g_wlo2[(size_t)NBLK * 32768];    // per-CTA W lo
__device__ __nv_bfloat16 g_hhi[kB * kH];                  // h bf16 hi [b][k]
__device__ __nv_bfloat16 g_hlo[kB * kH];                  // h bf16 lo
__device__ unsigned g_bar;

__device__ __forceinline__ uint32_t smem_u32(const void* p) {
    uint32_t a;
    asm("{ .reg .u64 t; cvta.to.shared.u64 t, %1; cvt.u32.u64 %0, t; }"
        : "=r"(a) : "l"(p));
    return a;
}
__device__ __forceinline__ void ldsm_x4(uint32_t* r, uint32_t addr) {
    asm volatile("ldmatrix.sync.aligned.m8n8.x4.shared.b16 {%0,%1,%2,%3}, [%4];"
                 : "=r"(r[0]), "=r"(r[1]), "=r"(r[2]), "=r"(r[3]) : "r"(addr));
}
__device__ __forceinline__ void mma_bf16(float* c, const uint32_t* a,
                                         uint32_t b0, uint32_t b1) {
    asm volatile(
        "mma.sync.aligned.m16n8k16.row.col.f32.bf16.bf16.f32 "
        "{%0,%1,%2,%3}, {%4,%5,%6,%7}, {%8,%9}, {%0,%1,%2,%3};"
        : "+f"(c[0]), "+f"(c[1]), "+f"(c[2]), "+f"(c[3])
        : "r"(a[0]), "r"(a[1]), "r"(a[2]), "r"(a[3]), "r"(b0), "r"(b1));
}
__device__ __forceinline__ float sigmoidf_(float x) {
    return 1.0f / (1.0f + __expf(-x));
}
__device__ __forceinline__ void fma2(ull& d, ull a, ull b) {
    asm("fma.rn.f32x2 %0, %1, %2, %0;" : "+l"(d) : "l"(a), "l"(b));
}
__device__ __forceinline__ float redpair(ull v) {
    float2 f = *reinterpret_cast<float2*>(&v);
    return f.x + f.y;
}

__global__ void reset_kernel() { g_bar = 0u; }

// ---------------------------------------------------------------------------
// Prep: fp32 recurrent W -> bf16 hi/lo, per-CTA [n=32][k=1024] rows.
// n = gate*8 + col; value = W[k][8*cta + col].
// ---------------------------------------------------------------------------
__global__ void __launch_bounds__(256) prep_weights(
    const float* __restrict__ Wf, const float* __restrict__ Wi,
    const float* __restrict__ Wc, const float* __restrict__ Wo)
{
    const int cta = blockIdx.x;
    const int n0h = cta * 8;
    for (int g = 0; g < 4; g++) {
        const float* W = (g == 0) ? Wf : (g == 1) ? Wi : (g == 2) ? Wc : Wo;
        for (int idx = threadIdx.x; idx < 8 * kH; idx += 256) {
            int col = idx & 7, r = idx >> 3;
            float v = W[(size_t)r * kH + n0h + col];
            __nv_bfloat16 hi = __float2bfloat16_rn(v);
            __nv_bfloat16 lo = __float2bfloat16_rn(v - __bfloat162float(hi));
            size_t o = (size_t)cta * 32768 + (size_t)(g * 8 + col) * kH + r;
            g_whi2[o] = hi;
            g_wlo2[o] = lo;
        }
    }
}

// ---------------------------------------------------------------------------
// Phase 1: gx = X @ Wx + b (exact fp32 scalar GEMM; proven).
// ---------------------------------------------------------------------------
static constexpr int P1_BM = 128;
static constexpr int P1_BN = 64;
static constexpr int P1_BK = 32;

__global__ void __launch_bounds__(256) phase1_kernel(
    const float* __restrict__ x,
    const float* __restrict__ Wf, const float* __restrict__ Wi,
    const float* __restrict__ Wc, const float* __restrict__ Wo,
    const float* __restrict__ bf, const float* __restrict__ bi,
    const float* __restrict__ bc, const float* __restrict__ bo)
{
    __shared__ float As[P1_BM][P1_BK + 4];
    __shared__ float Bsm[P1_BK / 2][P1_BN * 2];

    const int tid  = threadIdx.x;
    const int gate = blockIdx.x >> 4;
    const int n0   = (blockIdx.x & 15) * P1_BN;
    const int m0   = blockIdx.y * P1_BM;

    const float* W    = (gate == 0) ? Wf : (gate == 1) ? Wi : (gate == 2) ? Wc : Wo;
    const float* bias = (gate == 0) ? bf : (gate == 1) ? bi : (gate == 2) ? bc : bo;

    const int ng = tid & 7;
    const int mg = tid >> 3;

    ull acc[4][8];
#pragma unroll
    for (int i = 0; i < 4; i++)
#pragma unroll
        for (int j = 0; j < 8; j++) acc[i][j] = 0ull;

    float4 pa[4];
    float4 pb0, pb1;
    {
#pragma unroll
        for (int r = 0; r < 4; r++) {
            int idx = tid + r * 256;
            int m = idx >> 3, fk = idx & 7;
            pa[r] = *reinterpret_cast<const float4*>(&x[(size_t)(m0 + m) * kIN + 4 * fk]);
        }
        int kk = tid >> 3, fn = tid & 7;
        const float* wr = &W[(size_t)(kH + kk) * kH + n0 + 8 * fn];
        pb0 = *reinterpret_cast<const float4*>(wr);
        pb1 = *reinterpret_cast<const float4*>(wr + 4);
    }

    const int NCH = kIN / P1_BK;
    for (int c = 0; c < NCH; ++c) {
        __syncthreads();
#pragma unroll
        for (int r = 0; r < 4; r++) {
            int idx = tid + r * 256;
            int m = idx >> 3, fk = idx & 7;
            *reinterpret_cast<float4*>(&As[m][4 * fk]) = pa[r];
        }
        {
            int kk = tid >> 3, fn = tid & 7;
            float* brow = &Bsm[kk >> 1][0];
            int half = kk & 1;
            int vb = 8 * fn;
            brow[(vb + 0) * 2 + half] = pb0.x;
            brow[(vb + 1) * 2 + half] = pb0.y;
            brow[(vb + 2) * 2 + half] = pb0.z;
            brow[(vb + 3) * 2 + half] = pb0.w;
            brow[(vb + 4) * 2 + half] = pb1.x;
            brow[(vb + 5) * 2 + half] = pb1.y;
            brow[(vb + 6) * 2 + half] = pb1.z;
            brow[(vb + 7) * 2 + half] = pb1.w;
        }
        __syncthreads();
        if (c + 1 < NCH) {
            int kc = (c + 1) * P1_BK;
#pragma unroll
            for (int r = 0; r < 4; r++) {
                int idx = tid + r * 256;
                int m = idx >> 3, fk = idx & 7;
                pa[r] = *reinterpret_cast<const float4*>(&x[(size_t)(m0 + m) * kIN + kc + 4 * fk]);
            }
            int kk = tid >> 3, fn = tid & 7;
            const float* wr = &W[(size_t)(kH + kc + kk) * kH + n0 + 8 * fn];
            pb0 = *reinterpret_cast<const float4*>(wr);
            pb1 = *reinterpret_cast<const float4*>(wr + 4);
        }
#pragma unroll
        for (int k2 = 0; k2 < P1_BK / 2; ++k2) {
            ull a[4];
#pragma unroll
            for (int i = 0; i < 4; i++)
                a[i] = *reinterpret_cast<const ull*>(&As[4 * mg + i][2 * k2]);
            ull b[8];
#pragma unroll
            for (int s = 0; s < 4; s++) {
                float4 q = *reinterpret_cast<const float4*>(&Bsm[k2][16 * ng + 4 * s]);
                b[2 * s + 0] = reinterpret_cast<ull*>(&q)[0];
                b[2 * s + 1] = reinterpret_cast<ull*>(&q)[1];
            }
#pragma unroll
            for (int i = 0; i < 4; i++)
#pragma unroll
                for (int j = 0; j < 8; j++)
                    fma2(acc[i][j], a[i], b[j]);
        }
    }

    float4 bb0 = *reinterpret_cast<const float4*>(&bias[n0 + 8 * ng]);
    float4 bb1 = *reinterpret_cast<const float4*>(&bias[n0 + 8 * ng + 4]);
    const int cta = (n0 >> 3) + ng;
#pragma unroll
    for (int i = 0; i < 4; i++) {
        int m = m0 + 4 * mg + i;
        int t = m >> 6, b = m & 63;
        float* orow = &g_gx2[(((size_t)t * NBLK + cta) * kB + b) * 32 + gate * 8];
        float4 o0, o1;
        o0.x = redpair(acc[i][0]) + bb0.x;
        o0.y = redpair(acc[i][1]) + bb0.y;
        o0.z = redpair(acc[i][2]) + bb0.z;
        o0.w = redpair(acc[i][3]) + bb0.w;
        o1.x = redpair(acc[i][4]) + bb1.x;
        o1.y = redpair(acc[i][5]) + bb1.y;
        o1.z = redpair(acc[i][6]) + bb1.z;
        o1.w = redpair(acc[i][7]) + bb1.w;
        *reinterpret_cast<float4*>(orow) = o0;
        *reinterpret_cast<float4*>(orow + 4) = o1;
    }
}

// ---------------------------------------------------------------------------
// Persistent HMMA phase 2. 128 CTAs x 256 threads (8 warps: 4m x 2n).
// SMEM layout (bytes):
//   A hi  [64][136 bf16]  stride 272   : 17408
//   A lo                                : 17408
//   B hi  [32][1032 bf16] stride 2064  : 66048
//   B lo                                : 66048
//   pre_s [64][33] f32                  : 8448
//   c_s   [64][8]  f32                  : 2048
// ---------------------------------------------------------------------------
static constexpr uint32_t SA_STRIDE = 272;     // bytes per A row (128+8 bf16)
static constexpr uint32_t SB_STRIDE = 2064;    // bytes per B row (1024+8 bf16)
static constexpr uint32_t OFF_AHI = 0;
static constexpr uint32_t OFF_ALO = OFF_AHI + 64 * SA_STRIDE;          // 17408
static constexpr uint32_t OFF_BHI = OFF_ALO + 64 * SA_STRIDE;          // 34816
static constexpr uint32_t OFF_BLO = OFF_BHI + 32 * SB_STRIDE;          // 100864
static constexpr uint32_t OFF_PRE = OFF_BLO + 32 * SB_STRIDE;          // 166912
static constexpr uint32_t OFF_C   = OFF_PRE + 64 * 33 * 4;             // 175360
static constexpr uint32_t SM_TOTAL2 = OFF_C + 64 * 8 * 4;              // 177408

__global__ void __launch_bounds__(256, 1) lstm_hmma(float* __restrict__ out)
{
    extern __shared__ __align__(16) char smem[];
    const uint32_t sb = smem_u32(smem);
    float* pre_s = reinterpret_cast<float*>(smem + OFF_PRE);   // [64][33]
    float* c_s   = reinterpret_cast<float*>(smem + OFF_C);     // [64][8]

    const int tid  = threadIdx.x;
    const int wid  = tid >> 5;
    const int lane = tid & 31;
    const int bx   = blockIdx.x;
    const int n0h  = bx * 8;
    const int mi   = wid & 3;    // m-tile (16 rows)
    const int nj   = wid >> 2;   // n16 tile

    // ---- load resident weights (hi/lo) into padded smem rows ----
    {
        const uint4* shi = reinterpret_cast<const uint4*>(&g_whi2[(size_t)bx * 32768]);
        const uint4* slo = reinterpret_cast<const uint4*>(&g_wlo2[(size_t)bx * 32768]);
        for (int i = tid; i < 4096; i += 256) {          // 4096 uint4 = 32768 bf16
            int n = i >> 7, c8 = i & 127;                // 128 uint4 per n-row
            uint32_t o = n * SB_STRIDE + c8 * 16;
            *reinterpret_cast<uint4*>(smem + OFF_BHI + o) = shi[i];
            *reinterpret_cast<uint4*>(smem + OFF_BLO + o) = slo[i];
        }
    }
    // zero c state and h bf16 buffers (this CTA's slice)
    for (int i = tid; i < 512; i += 256) {
        c_s[i] = 0.0f;
        g_hhi[bx * 512 + i] = __float2bfloat16(0.0f);
        g_hlo[bx * 512 + i] = __float2bfloat16(0.0f);
    }
    __threadfence();
    __syncthreads();
    if (tid == 0) {
        atomicAdd(&g_bar, 1u);
        while (*((volatile unsigned*)&g_bar) < NBLK) { __nanosleep(32); }
    }
    __syncthreads();
    __threadfence();

    // per-lane ldmatrix base addresses
    const uint32_t a_row = 16 * mi + (lane & 15);
    const uint32_t a_k8  = (lane >> 4) * 8;
    const uint32_t aHiBase = sb + OFF_AHI + a_row * SA_STRIDE + a_k8 * 2;
    const uint32_t aLoBase = sb + OFF_ALO + a_row * SA_STRIDE + a_k8 * 2;
    const uint32_t b_row = 16 * nj + (lane & 7) + ((lane >> 4) << 3);
    const uint32_t b_k8  = ((lane >> 3) & 1) * 8;
    const uint32_t bHiBase = sb + OFF_BHI + b_row * SB_STRIDE + b_k8 * 2;
    const uint32_t bLoBase = sb + OFF_BLO + b_row * SB_STRIDE + b_k8 * 2;

    // A staging mapping: 512 uint4 per buffer (hi and lo), 2 each per thread
    const int st_row = tid >> 2;            // 0..63 (rows, 4 threads/row)
    const int st_c0  = (tid & 3) * 4;       // uint4 col within 16

    for (int t = 0; t < kT; ++t) {
        float C0[4] = {0.f, 0.f, 0.f, 0.f};
        float C1[4] = {0.f, 0.f, 0.f, 0.f};

        // prefetch chunk 0 of h (hi/lo)
        uint4 ph[4], pl[4];
#pragma unroll
        for (int r = 0; r < 4; ++r) {
            const size_t go = (size_t)st_row * kH + 0 + (st_c0 + r) * 8;
            ph[r] = *reinterpret_cast<const uint4*>(&g_hhi[go]);
            pl[r] = *reinterpret_cast<const uint4*>(&g_hlo[go]);
        }

        for (int c = 0; c < 8; ++c) {        // K chunks of 128
            __syncthreads();
#pragma unroll
            for (int r = 0; r < 4; ++r) {
                uint32_t so = st_row * SA_STRIDE + (st_c0 + r) * 16;
                *reinterpret_cast<uint4*>(smem + OFF_AHI + so) = ph[r];
                *reinterpret_cast<uint4*>(smem + OFF_ALO + so) = pl[r];
            }
            __syncthreads();
            if (c + 1 < 8) {
                const int kc = (c + 1) * 128;
#pragma unroll
                for (int r = 0; r < 4; ++r) {
                    const size_t go = (size_t)st_row * kH + kc + (st_c0 + r) * 8;
                    ph[r] = *reinterpret_cast<const uint4*>(&g_hhi[go]);
                    pl[r] = *reinterpret_cast<const uint4*>(&g_hlo[go]);
                }
            }
#pragma unroll
            for (int kk = 0; kk < 8; ++kk) {
                uint32_t ah[4], al[4], bh[4], bl[4];
                ldsm_x4(ah, aHiBase + kk * 32);
                ldsm_x4(al, aLoBase + kk * 32);
                const uint32_t bo = (uint32_t)(c * 128 + kk * 16) * 2;
                ldsm_x4(bh, bHiBase + bo);
                ldsm_x4(bl, bLoBase + bo);
                mma_bf16(C0, ah, bh[0], bh[1]);
                mma_bf16(C1, ah, bh[2], bh[3]);
                mma_bf16(C0, ah, bl[0], bl[1]);
                mma_bf16(C1, ah, bl[2], bl[3]);
                mma_bf16(C0, al, bh[0], bh[1]);
                mma_bf16(C1, al, bh[2], bh[3]);
            }
        }

        // ---- publish pre-activations ----
        {
            const int r0 = 16 * mi + (lane >> 2);
            const int cb = 16 * nj + (lane & 3) * 2;
            pre_s[r0 * 33 + cb + 0]       = C0[0];
            pre_s[r0 * 33 + cb + 1]       = C0[1];
            pre_s[(r0 + 8) * 33 + cb + 0] = C0[2];
            pre_s[(r0 + 8) * 33 + cb + 1] = C0[3];
            pre_s[r0 * 33 + cb + 8]       = C1[0];
            pre_s[r0 * 33 + cb + 9]       = C1[1];
            pre_s[(r0 + 8) * 33 + cb + 8] = C1[2];
            pre_s[(r0 + 8) * 33 + cb + 9] = C1[3];
        }
        __syncthreads();

        // ---- gate math + c/h update (512 items, 2/thread) ----
        const float* gx = &g_gx2[(((size_t)t * NBLK + bx) * kB) * 32];
#pragma unroll
        for (int r = 0; r < 2; ++r) {
            int idx = tid + r * 256;
            int b = idx >> 3, j = idx & 7;
            const float* gxr = gx + (size_t)b * 32;
            float pf = pre_s[b * 33 + j]      + gxr[j];
            float pi = pre_s[b * 33 + 8 + j]  + gxr[8 + j];
            float pg = pre_s[b * 33 + 16 + j] + gxr[16 + j];
            float po = pre_s[b * 33 + 24 + j] + gxr[24 + j];
            float f  = sigmoidf_(pf);
            float ii = sigmoidf_(pi);
            float gg = tanhf(pg);
            float oo = sigmoidf_(po);
            float cn = f * c_s[b * 8 + j] + ii * gg;
            c_s[b * 8 + j] = cn;
            float h = oo * tanhf(cn);
            out[(size_t)t * kBH + (size_t)b * kH + n0h + j] = h;
            __nv_bfloat16 bh16 = __float2bfloat16_rn(h);
            __nv_bfloat16 bl16 = __float2bfloat16_rn(h - __bfloat162float(bh16));
            g_hhi[b * kH + n0h + j] = bh16;
            g_hlo[b * kH + n0h + j] = bl16;
            if (t == kT - 1) {
                out[(size_t)kT * kBH + (size_t)b * kH + n0h + j] = h;
                out[(size_t)kT * kBH + kBH + (size_t)b * kH + n0h + j] = cn;
            }
        }

        // ---- global barrier between steps ----
        if (t < kT - 1) {
            __threadfence();
            __syncthreads();
            if (tid == 0) {
                atomicAdd(&g_bar, 1u);
                unsigned tgt = (unsigned)(t + 2) * NBLK;
                while (*((volatile unsigned*)&g_bar) < tgt) { __nanosleep(32); }
            }
            __syncthreads();
            __threadfence();
        }
    }
}

// ---------------------------------------------------------------------------
extern "C" void kernel_launch(void* const* d_in, const int* in_sizes, int n_in,
                              void* d_out, int out_size)
{
    const float* x  = (const float*)d_in[0];
    const float* Wf = (const float*)d_in[1];
    const float* bf = (const float*)d_in[2];
    const float* Wi = (const float*)d_in[3];
    const float* bi = (const float*)d_in[4];
    const float* Wc = (const float*)d_in[5];
    const float* bc = (const float*)d_in[6];
    const float* Wo = (const float*)d_in[7];
    const float* bo = (const float*)d_in[8];
    float* out = (float*)d_out;

    cudaFuncSetAttribute(lstm_hmma,
                         cudaFuncAttributeMaxDynamicSharedMemorySize, SM_TOTAL2);

    reset_kernel<<<1, 1>>>();
    prep_weights<<<NBLK, 256>>>(Wf, Wi, Wc, Wo);

    dim3 g1(64, kT * kB / P1_BM);
    phase1_kernel<<<g1, 256>>>(x, Wf, Wi, Wc, Wo, bf, bi, bc, bo);

    lstm_hmma<<<NBLK, 256, SM_TOTAL2>>>(out);
}

// round 6
// speedup vs baseline: 1.4252x; 1.0859x over previous
#include <cuda_runtime.h>
#include <cuda_bf16.h>
#include <cstdint>

// ---------------------------------------------------------------------------
// LSTM T=512, B=64, IN=512, H=1024.
// Phase 1 (scalar fp32 GEMM, exact): gx[t][cta][b][vn] = x_t @ Wx + bias.
// Phase 2 (persistent, 128 CTAs x 512 thr): recurrent GEMM h@Wh on
//   mma.sync.m16n8k16 bf16, 3-term hi/lo split, fp32 accum.
//   16 warps = 4 m-tiles x 2 n-tiles x 2 k-slices; two pre-activation
//   partial buffers summed in the gate update. Double-buffered A staging
//   (1 sync/chunk). Split global barrier: red.release arrive + ld.acquire
//   poll, gx prefetch in the gap.
// ---------------------------------------------------------------------------

static constexpr int kT  = 512;
static constexpr int kB  = 64;
static constexpr int kIN = 512;
static constexpr int kH  = 1024;
static constexpr int kBH = kB * kH;
static constexpr int NBLK = 128;

typedef unsigned long long ull;

__device__ float g_gx2[(size_t)kT * NBLK * kB * 32];      // [t][cta][b][vn]
__device__ __nv_bfloat16 g_whi2[(size_t)NBLK * 32768];    // per-CTA W hi [n=32][k=1024]
__device__ __nv_bfloat16 g_wlo2[(size_t)NBLK * 32768];    // per-CTA W lo
__device__ __nv_bfloat16 g_hhi[kB * kH];                  // h bf16 hi [b][k]
__device__ __nv_bfloat16 g_hlo[kB * kH];                  // h bf16 lo
__device__ unsigned g_bar;

__device__ __forceinline__ uint32_t smem_u32(const void* p) {
    uint32_t a;
    asm("{ .reg .u64 t; cvta.to.shared.u64 t, %1; cvt.u32.u64 %0, t; }"
        : "=r"(a) : "l"(p));
    return a;
}
__device__ __forceinline__ void ldsm_x4(uint32_t* r, uint32_t addr) {
    asm volatile("ldmatrix.sync.aligned.m8n8.x4.shared.b16 {%0,%1,%2,%3}, [%4];"
                 : "=r"(r[0]), "=r"(r[1]), "=r"(r[2]), "=r"(r[3]) : "r"(addr));
}
__device__ __forceinline__ void mma_bf16(float* c, const uint32_t* a,
                                         uint32_t b0, uint32_t b1) {
    asm volatile(
        "mma.sync.aligned.m16n8k16.row.col.f32.bf16.bf16.f32 "
        "{%0,%1,%2,%3}, {%4,%5,%6,%7}, {%8,%9}, {%0,%1,%2,%3};"
        : "+f"(c[0]), "+f"(c[1]), "+f"(c[2]), "+f"(c[3])
        : "r"(a[0]), "r"(a[1]), "r"(a[2]), "r"(a[3]), "r"(b0), "r"(b1));
}
__device__ __forceinline__ float sigmoidf_(float x) {
    return 1.0f / (1.0f + __expf(-x));
}
__device__ __forceinline__ void fma2(ull& d, ull a, ull b) {
    asm("fma.rn.f32x2 %0, %1, %2, %0;" : "+l"(d) : "l"(a), "l"(b));
}
__device__ __forceinline__ float redpair(ull v) {
    float2 f = *reinterpret_cast<float2*>(&v);
    return f.x + f.y;
}
__device__ __forceinline__ void bar_arrive_release(unsigned* p) {
    asm volatile("red.release.gpu.global.add.u32 [%0], 1;" :: "l"(p) : "memory");
}
__device__ __forceinline__ unsigned ld_acquire(unsigned* p) {
    unsigned v;
    asm volatile("ld.acquire.gpu.global.u32 %0, [%1];" : "=r"(v) : "l"(p) : "memory");
    return v;
}

__global__ void reset_kernel() { g_bar = 0u; }

// ---------------------------------------------------------------------------
// Prep: fp32 recurrent W -> bf16 hi/lo, per-CTA [n=32][k=1024] rows.
// ---------------------------------------------------------------------------
__global__ void __launch_bounds__(256) prep_weights(
    const float* __restrict__ Wf, const float* __restrict__ Wi,
    const float* __restrict__ Wc, const float* __restrict__ Wo)
{
    const int cta = blockIdx.x;
    const int n0h = cta * 8;
    for (int g = 0; g < 4; g++) {
        const float* W = (g == 0) ? Wf : (g == 1) ? Wi : (g == 2) ? Wc : Wo;
        for (int idx = threadIdx.x; idx < 8 * kH; idx += 256) {
            int col = idx & 7, r = idx >> 3;
            float v = W[(size_t)r * kH + n0h + col];
            __nv_bfloat16 hi = __float2bfloat16_rn(v);
            __nv_bfloat16 lo = __float2bfloat16_rn(v - __bfloat162float(hi));
            size_t o = (size_t)cta * 32768 + (size_t)(g * 8 + col) * kH + r;
            g_whi2[o] = hi;
            g_wlo2[o] = lo;
        }
    }
}

// ---------------------------------------------------------------------------
// Phase 1: gx = X @ Wx + b (exact fp32 scalar GEMM; proven).
// ---------------------------------------------------------------------------
static constexpr int P1_BM = 128;
static constexpr int P1_BN = 64;
static constexpr int P1_BK = 32;

__global__ void __launch_bounds__(256) phase1_kernel(
    const float* __restrict__ x,
    const float* __restrict__ Wf, const float* __restrict__ Wi,
    const float* __restrict__ Wc, const float* __restrict__ Wo,
    const float* __restrict__ bf, const float* __restrict__ bi,
    const float* __restrict__ bc, const float* __restrict__ bo)
{
    __shared__ float As[P1_BM][P1_BK + 4];
    __shared__ float Bsm[P1_BK / 2][P1_BN * 2];

    const int tid  = threadIdx.x;
    const int gate = blockIdx.x >> 4;
    const int n0   = (blockIdx.x & 15) * P1_BN;
    const int m0   = blockIdx.y * P1_BM;

    const float* W    = (gate == 0) ? Wf : (gate == 1) ? Wi : (gate == 2) ? Wc : Wo;
    const float* bias = (gate == 0) ? bf : (gate == 1) ? bi : (gate == 2) ? bc : bo;

    const int ng = tid & 7;
    const int mg = tid >> 3;

    ull acc[4][8];
#pragma unroll
    for (int i = 0; i < 4; i++)
#pragma unroll
        for (int j = 0; j < 8; j++) acc[i][j] = 0ull;

    float4 pa[4];
    float4 pb0, pb1;
    {
#pragma unroll
        for (int r = 0; r < 4; r++) {
            int idx = tid + r * 256;
            int m = idx >> 3, fk = idx & 7;
            pa[r] = *reinterpret_cast<const float4*>(&x[(size_t)(m0 + m) * kIN + 4 * fk]);
        }
        int kk = tid >> 3, fn = tid & 7;
        const float* wr = &W[(size_t)(kH + kk) * kH + n0 + 8 * fn];
        pb0 = *reinterpret_cast<const float4*>(wr);
        pb1 = *reinterpret_cast<const float4*>(wr + 4);
    }

    const int NCH = kIN / P1_BK;
    for (int c = 0; c < NCH; ++c) {
        __syncthreads();
#pragma unroll
        for (int r = 0; r < 4; r++) {
            int idx = tid + r * 256;
            int m = idx >> 3, fk = idx & 7;
            *reinterpret_cast<float4*>(&As[m][4 * fk]) = pa[r];
        }
        {
            int kk = tid >> 3, fn = tid & 7;
            float* brow = &Bsm[kk >> 1][0];
            int half = kk & 1;
            int vb = 8 * fn;
            brow[(vb + 0) * 2 + half] = pb0.x;
            brow[(vb + 1) * 2 + half] = pb0.y;
            brow[(vb + 2) * 2 + half] = pb0.z;
            brow[(vb + 3) * 2 + half] = pb0.w;
            brow[(vb + 4) * 2 + half] = pb1.x;
            brow[(vb + 5) * 2 + half] = pb1.y;
            brow[(vb + 6) * 2 + half] = pb1.z;
            brow[(vb + 7) * 2 + half] = pb1.w;
        }
        __syncthreads();
        if (c + 1 < NCH) {
            int kc = (c + 1) * P1_BK;
#pragma unroll
            for (int r = 0; r < 4; r++) {
                int idx = tid + r * 256;
                int m = idx >> 3, fk = idx & 7;
                pa[r] = *reinterpret_cast<const float4*>(&x[(size_t)(m0 + m) * kIN + kc + 4 * fk]);
            }
            int kk = tid >> 3, fn = tid & 7;
            const float* wr = &W[(size_t)(kH + kc + kk) * kH + n0 + 8 * fn];
            pb0 = *reinterpret_cast<const float4*>(wr);
            pb1 = *reinterpret_cast<const float4*>(wr + 4);
        }
#pragma unroll
        for (int k2 = 0; k2 < P1_BK / 2; ++k2) {
            ull a[4];
#pragma unroll
            for (int i = 0; i < 4; i++)
                a[i] = *reinterpret_cast<const ull*>(&As[4 * mg + i][2 * k2]);
            ull b[8];
#pragma unroll
            for (int s = 0; s < 4; s++) {
                float4 q = *reinterpret_cast<const float4*>(&Bsm[k2][16 * ng + 4 * s]);
                b[2 * s + 0] = reinterpret_cast<ull*>(&q)[0];
                b[2 * s + 1] = reinterpret_cast<ull*>(&q)[1];
            }
#pragma unroll
            for (int i = 0; i < 4; i++)
#pragma unroll
                for (int j = 0; j < 8; j++)
                    fma2(acc[i][j], a[i], b[j]);
        }
    }

    float4 bb0 = *reinterpret_cast<const float4*>(&bias[n0 + 8 * ng]);
    float4 bb1 = *reinterpret_cast<const float4*>(&bias[n0 + 8 * ng + 4]);
    const int cta = (n0 >> 3) + ng;
#pragma unroll
    for (int i = 0; i < 4; i++) {
        int m = m0 + 4 * mg + i;
        int t = m >> 6, b = m & 63;
        float* orow = &g_gx2[(((size_t)t * NBLK + cta) * kB + b) * 32 + gate * 8];
        float4 o0, o1;
        o0.x = redpair(acc[i][0]) + bb0.x;
        o0.y = redpair(acc[i][1]) + bb0.y;
        o0.z = redpair(acc[i][2]) + bb0.z;
        o0.w = redpair(acc[i][3]) + bb0.w;
        o1.x = redpair(acc[i][4]) + bb1.x;
        o1.y = redpair(acc[i][5]) + bb1.y;
        o1.z = redpair(acc[i][6]) + bb1.z;
        o1.w = redpair(acc[i][7]) + bb1.w;
        *reinterpret_cast<float4*>(orow) = o0;
        *reinterpret_cast<float4*>(orow + 4) = o1;
    }
}

// ---------------------------------------------------------------------------
// Persistent HMMA phase 2, v2. 128 CTAs x 512 threads (16 warps).
// Warp w: mi = w&3 (m16), nj = (w>>2)&1 (n16), ks = w>>3 (k16 units 4ks..4ks+3
// of the current 128-k chunk). Two pre buffers (ks partials).
// SMEM: B hi/lo resident, A double-buffered (hi/lo), preA/preB, c.
// ---------------------------------------------------------------------------
static constexpr uint32_t SA_STRIDE = 272;     // bytes per A row (128+8 bf16)
static constexpr uint32_t SB_STRIDE = 2064;    // bytes per B row (1024+8 bf16)
static constexpr uint32_t A_BUF = 64 * SA_STRIDE;                    // 17408
static constexpr uint32_t OFF_BHI = 0;
static constexpr uint32_t OFF_BLO = OFF_BHI + 32 * SB_STRIDE;        // 66048
static constexpr uint32_t OFF_A   = OFF_BLO + 32 * SB_STRIDE;        // 132096
// A layout: buf0hi, buf0lo, buf1hi, buf1lo (each A_BUF)
static constexpr uint32_t OFF_PREA = OFF_A + 4 * A_BUF;              // 201728
static constexpr uint32_t OFF_PREB = OFF_PREA + 64 * 33 * 4;         // 210176
static constexpr uint32_t OFF_C    = OFF_PREB + 64 * 33 * 4;         // 218624
static constexpr uint32_t SM_TOTAL2 = OFF_C + 512 * 4;               // 220672

__global__ void __launch_bounds__(512, 1) lstm_hmma2(float* __restrict__ out)
{
    extern __shared__ __align__(16) char smem[];
    const uint32_t sb = smem_u32(smem);
    float* preA = reinterpret_cast<float*>(smem + OFF_PREA);   // [64][33]
    float* preB = reinterpret_cast<float*>(smem + OFF_PREB);   // [64][33]
    float* c_s  = reinterpret_cast<float*>(smem + OFF_C);      // [512]

    const int tid  = threadIdx.x;
    const int wid  = tid >> 5;
    const int lane = tid & 31;
    const int bx   = blockIdx.x;
    const int n0h  = bx * 8;
    const int mi   = wid & 3;
    const int nj   = (wid >> 2) & 1;
    const int ks   = wid >> 3;

    // ---- resident weights ----
    {
        const uint4* shi = reinterpret_cast<const uint4*>(&g_whi2[(size_t)bx * 32768]);
        const uint4* slo = reinterpret_cast<const uint4*>(&g_wlo2[(size_t)bx * 32768]);
        for (int i = tid; i < 4096; i += 512) {
            int n = i >> 7, c8 = i & 127;
            uint32_t o = n * SB_STRIDE + c8 * 16;
            *reinterpret_cast<uint4*>(smem + OFF_BHI + o) = shi[i];
            *reinterpret_cast<uint4*>(smem + OFF_BLO + o) = slo[i];
        }
    }
    // zero c state and h buffers (this CTA's slice: 512 elems, 1/thread)
    c_s[tid] = 0.0f;
    g_hhi[bx * 512 + tid] = __float2bfloat16(0.0f);
    g_hlo[bx * 512 + tid] = __float2bfloat16(0.0f);
    __syncthreads();
    if (tid == 0) {
        bar_arrive_release(&g_bar);
        while (ld_acquire(&g_bar) < NBLK) { __nanosleep(16); }
    }
    __syncthreads();

    // per-lane ldmatrix bases (fragment mappings identical to the proven R5)
    const uint32_t a_row = 16 * mi + (lane & 15);
    const uint32_t a_off = a_row * SA_STRIDE + (lane >> 4) * 16;
    const uint32_t b_row = 16 * nj + (lane & 7) + ((lane >> 4) << 3);
    const uint32_t bHiBase = sb + OFF_BHI + b_row * SB_STRIDE + ((lane >> 3) & 1) * 16;
    const uint32_t bLoBase = sb + OFF_BLO + b_row * SB_STRIDE + ((lane >> 3) & 1) * 16;

    // staging mapping: thread -> (row, 2 consecutive uint4 cols)
    const int st_row = tid >> 3;            // 0..63
    const int st_c   = (tid & 7) * 2;       // uint4 col (even)
    const uint32_t st_so = st_row * SA_STRIDE + st_c * 16;
    const size_t  st_go = (size_t)st_row * kH + st_c * 8;

    // gate-update mapping: 1 item/thread
    const int ub = tid >> 3, uj = tid & 7;

    // gx prefetch for t=0
    float gx4[4];
    {
        const float* gx = &g_gx2[(((size_t)0 * NBLK + bx) * kB + ub) * 32];
#pragma unroll
        for (int g = 0; g < 4; ++g) gx4[g] = gx[8 * g + uj];
    }

    for (int t = 0; t < kT; ++t) {
        float C0[4] = {0.f, 0.f, 0.f, 0.f};
        float C1[4] = {0.f, 0.f, 0.f, 0.f};

        // prefetch chunk 0
        uint4 ph[2], pl[2];
        ph[0] = *reinterpret_cast<const uint4*>(&g_hhi[st_go]);
        ph[1] = *reinterpret_cast<const uint4*>(&g_hhi[st_go + 8]);
        pl[0] = *reinterpret_cast<const uint4*>(&g_hlo[st_go]);
        pl[1] = *reinterpret_cast<const uint4*>(&g_hlo[st_go + 8]);

        for (int c = 0; c < 8; ++c) {        // K chunks of 128
            const uint32_t bhi = OFF_A + (uint32_t)(c & 1) * (2 * A_BUF);
            const uint32_t blo = bhi + A_BUF;
            *reinterpret_cast<uint4*>(smem + bhi + st_so)      = ph[0];
            *reinterpret_cast<uint4*>(smem + bhi + st_so + 16) = ph[1];
            *reinterpret_cast<uint4*>(smem + blo + st_so)      = pl[0];
            *reinterpret_cast<uint4*>(smem + blo + st_so + 16) = pl[1];
            __syncthreads();
            if (c + 1 < 8) {
                const size_t go = st_go + (size_t)(c + 1) * 128;
                ph[0] = *reinterpret_cast<const uint4*>(&g_hhi[go]);
                ph[1] = *reinterpret_cast<const uint4*>(&g_hhi[go + 8]);
                pl[0] = *reinterpret_cast<const uint4*>(&g_hlo[go]);
                pl[1] = *reinterpret_cast<const uint4*>(&g_hlo[go + 8]);
            }
            const uint32_t aHiBase = sb + bhi + a_off;
            const uint32_t aLoBase = sb + blo + a_off;
#pragma unroll
            for (int kk = 0; kk < 4; ++kk) {
                const int u = 4 * ks + kk;               // k16 unit in chunk
                uint32_t ah[4], al[4], bh[4], bl[4];
                ldsm_x4(ah, aHiBase + u * 32);
                ldsm_x4(al, aLoBase + u * 32);
                const uint32_t bo = (uint32_t)(c * 256 + u * 32);
                ldsm_x4(bh, bHiBase + bo);
                ldsm_x4(bl, bLoBase + bo);
                mma_bf16(C0, ah, bh[0], bh[1]);
                mma_bf16(C1, ah, bh[2], bh[3]);
                mma_bf16(C0, ah, bl[0], bl[1]);
                mma_bf16(C1, ah, bl[2], bl[3]);
                mma_bf16(C0, al, bh[0], bh[1]);
                mma_bf16(C1, al, bh[2], bh[3]);
            }
        }

        // ---- publish partial pre-activations (two buffers, by k-slice) ----
        {
            float* pre = ks ? preB : preA;
            const int r0 = 16 * mi + (lane >> 2);
            const int cb = 16 * nj + (lane & 3) * 2;
            pre[r0 * 33 + cb + 0]       = C0[0];
            pre[r0 * 33 + cb + 1]       = C0[1];
            pre[(r0 + 8) * 33 + cb + 0] = C0[2];
            pre[(r0 + 8) * 33 + cb + 1] = C0[3];
            pre[r0 * 33 + cb + 8]       = C1[0];
            pre[r0 * 33 + cb + 9]       = C1[1];
            pre[(r0 + 8) * 33 + cb + 8] = C1[2];
            pre[(r0 + 8) * 33 + cb + 9] = C1[3];
        }
        __syncthreads();

        // ---- gate math + c/h update (1 item/thread) ----
        {
            const int b = ub, j = uj;
            float pf = preA[b * 33 + j]      + preB[b * 33 + j]      + gx4[0];
            float pi = preA[b * 33 + 8 + j]  + preB[b * 33 + 8 + j]  + gx4[1];
            float pg = preA[b * 33 + 16 + j] + preB[b * 33 + 16 + j] + gx4[2];
            float po = preA[b * 33 + 24 + j] + preB[b * 33 + 24 + j] + gx4[3];
            float f  = sigmoidf_(pf);
            float ii = sigmoidf_(pi);
            float gg = tanhf(pg);
            float oo = sigmoidf_(po);
            float cn = f * c_s[tid] + ii * gg;
            c_s[tid] = cn;
            float h = oo * tanhf(cn);
            out[(size_t)t * kBH + (size_t)b * kH + n0h + j] = h;
            __nv_bfloat16 bh16 = __float2bfloat16_rn(h);
            __nv_bfloat16 bl16 = __float2bfloat16_rn(h - __bfloat162float(bh16));
            g_hhi[b * kH + n0h + j] = bh16;
            g_hlo[b * kH + n0h + j] = bl16;
            if (t == kT - 1) {
                out[(size_t)kT * kBH + (size_t)b * kH + n0h + j] = h;
                out[(size_t)kT * kBH + kBH + (size_t)b * kH + n0h + j] = cn;
            }
        }

        // ---- split global barrier (release arrive, gx prefetch, acquire wait)
        if (t < kT - 1) {
            __syncthreads();                 // all h stores done in this CTA
            if (tid == 0) bar_arrive_release(&g_bar);
            {
                const float* gx = &g_gx2[(((size_t)(t + 1) * NBLK + bx) * kB + ub) * 32];
#pragma unroll
                for (int g = 0; g < 4; ++g) gx4[g] = gx[8 * g + uj];
            }
            if (tid == 0) {
                const unsigned tgt = (unsigned)(t + 2) * NBLK;
                while (ld_acquire(&g_bar) < tgt) { __nanosleep(16); }
            }
            __syncthreads();
        }
    }
}

// ---------------------------------------------------------------------------
extern "C" void kernel_launch(void* const* d_in, const int* in_sizes, int n_in,
                              void* d_out, int out_size)
{
    const float* x  = (const float*)d_in[0];
    const float* Wf = (const float*)d_in[1];
    const float* bf = (const float*)d_in[2];
    const float* Wi = (const float*)d_in[3];
    const float* bi = (const float*)d_in[4];
    const float* Wc = (const float*)d_in[5];
    const float* bc = (const float*)d_in[6];
    const float* Wo = (const float*)d_in[7];
    const float* bo = (const float*)d_in[8];
    float* out = (float*)d_out;

    cudaFuncSetAttribute(lstm_hmma2,
                         cudaFuncAttributeMaxDynamicSharedMemorySize, SM_TOTAL2);

    reset_kernel<<<1, 1>>>();
    prep_weights<<<NBLK, 256>>>(Wf, Wi, Wc, Wo);

    dim3 g1(64, kT * kB / P1_BM);
    phase1_kernel<<<g1, 256>>>(x, Wf, Wi, Wc, Wo, bf, bi, bc, bo);

    lstm_hmma2<<<NBLK, 512, SM_TOTAL2>>>(out);
}

// round 9
// speedup vs baseline: 3.6525x; 2.5628x over previous
#include <cuda_runtime.h>
#include <cuda_bf16.h>
#include <cstdint>

// ---------------------------------------------------------------------------
// LSTM T=512, B=64, IN=512, H=1024.
// Phase 1 (HMMA bf16 3-term split): gx[t][cta][b][vn] = x_t @ Wx + bias.
// Phase 2 (persistent, 128 CTAs x 512 thr): recurrent GEMM h@Wh on
//   mma.sync.m16n8k16 bf16, 3-term hi/lo split, fp32 accum.
//   16 warps = 4 m-tiles x 4 k-slices, each warp n=32 (no A duplication).
//   A staged via cp.async.cg 3-buffer ring (2 chunks ahead, 1 sync/chunk).
//   4 pre-activation partial buffers (stride 34 -> float2-aligned).
//   Split global barrier: red.release arrive + ld.acquire poll.
// ---------------------------------------------------------------------------

static constexpr int kT  = 512;
static constexpr int kB  = 64;
static constexpr int kIN = 512;
static constexpr int kH  = 1024;
static constexpr int kBH = kB * kH;
static constexpr int NBLK = 128;

__device__ float g_gx2[(size_t)kT * NBLK * kB * 32];      // [t][cta][b][vn]
__device__ __nv_bfloat16 g_whi2[(size_t)NBLK * 32768];    // per-CTA Wh hi [n=32][k=1024]
__device__ __nv_bfloat16 g_wlo2[(size_t)NBLK * 32768];    // per-CTA Wh lo
__device__ __nv_bfloat16 g_hhi[kB * kH];                  // h bf16 hi [b][k]
__device__ __nv_bfloat16 g_hlo[kB * kH];                  // h bf16 lo
__device__ __nv_bfloat16 g_xhi[(size_t)kT * kB * kIN];    // x hi [m][k]
__device__ __nv_bfloat16 g_xlo[(size_t)kT * kB * kIN];    // x lo
__device__ __nv_bfloat16 g_wxhi[(size_t)4096 * kIN];      // Wx hi [n=4096][k=512]
__device__ __nv_bfloat16 g_wxlo[(size_t)4096 * kIN];      // Wx lo
__device__ unsigned g_bar;

__device__ __forceinline__ uint32_t smem_u32(const void* p) {
    uint32_t a;
    asm("{ .reg .u64 t; cvta.to.shared.u64 t, %1; cvt.u32.u64 %0, t; }"
        : "=r"(a) : "l"(p));
    return a;
}
__device__ __forceinline__ void ldsm_x4(uint32_t* r, uint32_t addr) {
    asm volatile("ldmatrix.sync.aligned.m8n8.x4.shared.b16 {%0,%1,%2,%3}, [%4];"
                 : "=r"(r[0]), "=r"(r[1]), "=r"(r[2]), "=r"(r[3]) : "r"(addr));
}
__device__ __forceinline__ void mma_bf16(float* c, const uint32_t* a,
                                         uint32_t b0, uint32_t b1) {
    asm volatile(
        "mma.sync.aligned.m16n8k16.row.col.f32.bf16.bf16.f32 "
        "{%0,%1,%2,%3}, {%4,%5,%6,%7}, {%8,%9}, {%0,%1,%2,%3};"
        : "+f"(c[0]), "+f"(c[1]), "+f"(c[2]), "+f"(c[3])
        : "r"(a[0]), "r"(a[1]), "r"(a[2]), "r"(a[3]), "r"(b0), "r"(b1));
}
__device__ __forceinline__ void cp16(uint32_t dst, const void* src) {
    asm volatile("cp.async.cg.shared.global [%0], [%1], 16;"
                 :: "r"(dst), "l"(src) : "memory");
}
__device__ __forceinline__ void cp_commit() {
    asm volatile("cp.async.commit_group;" ::: "memory");
}
__device__ __forceinline__ void cp_wait1() {
    asm volatile("cp.async.wait_group 1;" ::: "memory");
}
__device__ __forceinline__ void cp_wait0() {
    asm volatile("cp.async.wait_group 0;" ::: "memory");
}
__device__ __forceinline__ float sigmoidf_(float x) {
    return 1.0f / (1.0f + __expf(-x));
}
__device__ __forceinline__ void bar_arrive_release(unsigned* p) {
    asm volatile("red.release.gpu.global.add.u32 [%0], 1;" :: "l"(p) : "memory");
}
__device__ __forceinline__ unsigned ld_acquire(unsigned* p) {
    unsigned v;
    asm volatile("ld.acquire.gpu.global.u32 %0, [%1];" : "=r"(v) : "l"(p) : "memory");
    return v;
}

__global__ void reset_kernel() { g_bar = 0u; }

// ---------------------------------------------------------------------------
// Prep kernels: fp32 -> bf16 hi/lo
// ---------------------------------------------------------------------------
__device__ __forceinline__ void split_bf16(float v, __nv_bfloat16& hi, __nv_bfloat16& lo) {
    hi = __float2bfloat16_rn(v);
    lo = __float2bfloat16_rn(v - __bfloat162float(hi));
}

__global__ void __launch_bounds__(256) prep_x(const float* __restrict__ x) {
    size_t i = (size_t)blockIdx.x * 256 + threadIdx.x;
    __nv_bfloat16 hi, lo;
    split_bf16(x[i], hi, lo);
    g_xhi[i] = hi; g_xlo[i] = lo;
}

__global__ void __launch_bounds__(256) prep_wx(
    const float* __restrict__ Wf, const float* __restrict__ Wi,
    const float* __restrict__ Wc, const float* __restrict__ Wo)
{
    size_t i = (size_t)blockIdx.x * 256 + threadIdx.x;   // 4096*512 total
    int n = (int)(i >> 9), k = (int)(i & 511);
    int gate = n >> 10, h = n & 1023;
    const float* W = (gate == 0) ? Wf : (gate == 1) ? Wi : (gate == 2) ? Wc : Wo;
    __nv_bfloat16 hi, lo;
    split_bf16(W[(size_t)(kH + k) * kH + h], hi, lo);
    g_wxhi[i] = hi; g_wxlo[i] = lo;
}

__global__ void __launch_bounds__(256) prep_weights(
    const float* __restrict__ Wf, const float* __restrict__ Wi,
    const float* __restrict__ Wc, const float* __restrict__ Wo)
{
    const int cta = blockIdx.x;
    const int n0h = cta * 8;
    for (int g = 0; g < 4; g++) {
        const float* W = (g == 0) ? Wf : (g == 1) ? Wi : (g == 2) ? Wc : Wo;
        for (int idx = threadIdx.x; idx < 8 * kH; idx += 256) {
            int col = idx & 7, r = idx >> 3;
            __nv_bfloat16 hi, lo;
            split_bf16(W[(size_t)r * kH + n0h + col], hi, lo);
            size_t o = (size_t)cta * 32768 + (size_t)(g * 8 + col) * kH + r;
            g_whi2[o] = hi;
            g_wlo2[o] = lo;
        }
    }
}

// ---------------------------------------------------------------------------
// Phase 1 HMMA: gx = X @ Wx + b.  M=32768, N=4096, K=512.
// Tile BM=128 x BN=128 x BK=64. 512 thr, 16 warps = 4 m32 x 4 n32.
// ---------------------------------------------------------------------------
static constexpr uint32_t P1_AB = 18432;   // 128 rows * 144 B
static constexpr uint32_t P1_OFFB = 4 * P1_AB;          // 73728
static constexpr uint32_t P1_SM = 8 * P1_AB;            // 147456

__global__ void __launch_bounds__(512, 1) phase1_hmma(
    const float* __restrict__ bf, const float* __restrict__ bi,
    const float* __restrict__ bc, const float* __restrict__ bo)
{
    extern __shared__ __align__(128) char smem[];
    const uint32_t sb = smem_u32(smem);
    const int tid  = threadIdx.x;
    const int wid  = tid >> 5;
    const int lane = tid & 31;
    const int mi2  = wid & 3;
    const int nw   = wid >> 2;
    const int n0   = blockIdx.x * 128;
    const int m0   = blockIdx.y * 128;
    const int gate = n0 >> 10;
    const float* biasg = (gate == 0) ? bf : (gate == 1) ? bi : (gate == 2) ? bc : bo;

    const int s_row0 = tid >> 3, s_c16 = tid & 7;
    const int s_row1 = (tid + 512) >> 3;
    const uint32_t so0 = (uint32_t)(s_row0 * 144 + s_c16 * 16);
    const uint32_t so1 = (uint32_t)(s_row1 * 144 + s_c16 * 16);

    auto stage = [&](int c) {
        const int buf = c & 1;
        const uint32_t ahi = sb + buf * 2 * P1_AB;
        const uint32_t alo = ahi + P1_AB;
        const uint32_t bhi = sb + P1_OFFB + buf * 2 * P1_AB;
        const uint32_t blo = bhi + P1_AB;
        const size_t ga0 = (size_t)(m0 + s_row0) * kIN + c * 64 + s_c16 * 8;
        const size_t ga1 = (size_t)(m0 + s_row1) * kIN + c * 64 + s_c16 * 8;
        const size_t gb0 = (size_t)(n0 + s_row0) * kIN + c * 64 + s_c16 * 8;
        const size_t gb1 = (size_t)(n0 + s_row1) * kIN + c * 64 + s_c16 * 8;
        cp16(ahi + so0, &g_xhi[ga0]);  cp16(ahi + so1, &g_xhi[ga1]);
        cp16(alo + so0, &g_xlo[ga0]);  cp16(alo + so1, &g_xlo[ga1]);
        cp16(bhi + so0, &g_wxhi[gb0]); cp16(bhi + so1, &g_wxhi[gb1]);
        cp16(blo + so0, &g_wxlo[gb0]); cp16(blo + so1, &g_wxlo[gb1]);
    };

    uint32_t aoff[2];
#pragma unroll
    for (int i = 0; i < 2; i++)
        aoff[i] = (uint32_t)((32 * mi2 + 16 * i + (lane & 15)) * 144 + (lane >> 4) * 16);
    uint32_t boff[2];
#pragma unroll
    for (int j = 0; j < 2; j++)
        boff[j] = (uint32_t)((32 * nw + 16 * j + (lane & 7) + ((lane >> 4) << 3)) * 144
                             + ((lane >> 3) & 1) * 16);

    float C[2][2][2][4];
#pragma unroll
    for (int i = 0; i < 2; i++)
#pragma unroll
        for (int j = 0; j < 2; j++)
#pragma unroll
            for (int h2 = 0; h2 < 2; h2++)
#pragma unroll
                for (int q = 0; q < 4; q++) C[i][j][h2][q] = 0.0f;

    stage(0); cp_commit();

    for (int c = 0; c < 8; ++c) {
        if (c + 1 < 8) stage(c + 1);
        cp_commit();
        if (c + 1 < 8) cp_wait1(); else cp_wait0();
        __syncthreads();
        const int buf = c & 1;
        const uint32_t ahi = sb + buf * 2 * P1_AB;
        const uint32_t alo = ahi + P1_AB;
        const uint32_t bhi = sb + P1_OFFB + buf * 2 * P1_AB;
        const uint32_t blo = bhi + P1_AB;
#pragma unroll
        for (int u = 0; u < 4; ++u) {
            uint32_t ah[2][4], al[2][4], bh[2][4], bl[2][4];
#pragma unroll
            for (int i = 0; i < 2; i++) {
                ldsm_x4(ah[i], ahi + aoff[i] + u * 32);
                ldsm_x4(al[i], alo + aoff[i] + u * 32);
            }
#pragma unroll
            for (int j = 0; j < 2; j++) {
                ldsm_x4(bh[j], bhi + boff[j] + u * 32);
                ldsm_x4(bl[j], blo + boff[j] + u * 32);
            }
#pragma unroll
            for (int i = 0; i < 2; i++)
#pragma unroll
                for (int j = 0; j < 2; j++) {
                    mma_bf16(C[i][j][0], ah[i], bh[j][0], bh[j][1]);
                    mma_bf16(C[i][j][1], ah[i], bh[j][2], bh[j][3]);
                    mma_bf16(C[i][j][0], ah[i], bl[j][0], bl[j][1]);
                    mma_bf16(C[i][j][1], ah[i], bl[j][2], bl[j][3]);
                    mma_bf16(C[i][j][0], al[i], bh[j][0], bh[j][1]);
                    mma_bf16(C[i][j][1], al[i], bh[j][2], bh[j][3]);
                }
        }
        __syncthreads();
    }

    // epilogue: bias + scattered gx2 stores (float2, even offsets)
#pragma unroll
    for (int j = 0; j < 2; j++)
#pragma unroll
        for (int h2 = 0; h2 < 2; h2++) {
            const int col = 32 * nw + 16 * j + 8 * h2 + (lane & 3) * 2;
            const int n = n0 + col;
            const int hh = n & 1023;
            const int cta = hh >> 3, jj = hh & 7;
            const float b0 = biasg[hh], b1 = biasg[hh + 1];
#pragma unroll
            for (int i = 0; i < 2; i++)
#pragma unroll
                for (int rr = 0; rr < 2; rr++) {
                    const int r = 32 * mi2 + 16 * i + (lane >> 2) + 8 * rr;
                    const int m = m0 + r;
                    const int t = m >> 6, b = m & 63;
                    float2 v;
                    v.x = C[i][j][h2][2 * rr]     + b0;
                    v.y = C[i][j][h2][2 * rr + 1] + b1;
                    *reinterpret_cast<float2*>(
                        &g_gx2[(((size_t)t * NBLK + cta) * kB + b) * 32 + gate * 8 + jj]) = v;
                }
        }
}

// ---------------------------------------------------------------------------
// Persistent HMMA phase 2, v3 (fixed staging). 128 CTAs x 512 threads.
// Warp w: mi = w&3 (m16), ks = w>>2 (k-slice), each warp n=32.
// A chunk = 64 rows x 64 bf16 = 512 x 16B slots = exactly 1 cp16/thread/array.
// ---------------------------------------------------------------------------
static constexpr uint32_t SB_STRIDE = 2064;
static constexpr uint32_t OFF_BHI = 0;
static constexpr uint32_t OFF_BLO = 32 * SB_STRIDE;              // 66048
static constexpr uint32_t OFF_A   = 2 * 32 * SB_STRIDE;          // 132096
static constexpr uint32_t ABUF    = 9216;                        // 64 * 144
static constexpr int      PRE_STRIDE = 34;                       // floats (even!)
static constexpr int      PRE_FLOATS = 64 * PRE_STRIDE;          // 2176
static constexpr uint32_t OFF_PRE = OFF_A + 3 * 2 * ABUF;        // 187392
static constexpr uint32_t OFF_C   = OFF_PRE + 4 * PRE_FLOATS * 4;// 222208
static constexpr uint32_t SM_TOTAL2 = OFF_C + 2048;              // 224256

__global__ void __launch_bounds__(512, 1) lstm_hmma3(float* __restrict__ out)
{
    extern __shared__ __align__(128) char smem[];
    const uint32_t sb = smem_u32(smem);
    float* c_s = reinterpret_cast<float*>(smem + OFF_C);

    const int tid  = threadIdx.x;
    const int wid  = tid >> 5;
    const int lane = tid & 31;
    const int bx   = blockIdx.x;
    const int n0h  = bx * 8;
    const int mi   = wid & 3;
    const int ks   = wid >> 2;

    // resident weights
    {
        const uint4* shi = reinterpret_cast<const uint4*>(&g_whi2[(size_t)bx * 32768]);
        const uint4* slo = reinterpret_cast<const uint4*>(&g_wlo2[(size_t)bx * 32768]);
        for (int i = tid; i < 4096; i += 512) {
            int n = i >> 7, c8 = i & 127;
            uint32_t o = n * SB_STRIDE + c8 * 16;
            *reinterpret_cast<uint4*>(smem + OFF_BHI + o) = shi[i];
            *reinterpret_cast<uint4*>(smem + OFF_BLO + o) = slo[i];
        }
    }
    c_s[tid] = 0.0f;
    g_hhi[bx * 512 + tid] = __float2bfloat16(0.0f);
    g_hlo[bx * 512 + tid] = __float2bfloat16(0.0f);
    __syncthreads();
    if (tid == 0) {
        bar_arrive_release(&g_bar);
        while (ld_acquire(&g_bar) < NBLK) { __nanosleep(16); }
    }
    __syncthreads();

    // fragment bases
    const uint32_t a_off = (uint32_t)((16 * mi + (lane & 15)) * 144
                                      + (lane >> 4) * 16 + ks * 32);
    uint32_t bHi[2], bLo[2];
#pragma unroll
    for (int j = 0; j < 2; j++) {
        const uint32_t b_row = 16 * j + (lane & 7) + ((lane >> 4) << 3);
        bHi[j] = sb + OFF_BHI + b_row * SB_STRIDE + ((lane >> 3) & 1) * 16;
        bLo[j] = sb + OFF_BLO + b_row * SB_STRIDE + ((lane >> 3) & 1) * 16;
    }

    // staging: exactly ONE 16B slot per thread per array (64 rows x 8 uint4)
    const int s_row0 = tid >> 3, s_c16 = tid & 7;
    const uint32_t so0 = (uint32_t)(s_row0 * 144 + s_c16 * 16);

    // gate-update mapping
    const int ub = tid >> 3, uj = tid & 7;
    float* pre0 = reinterpret_cast<float*>(smem + OFF_PRE);
    float* pre1 = pre0 + PRE_FLOATS;
    float* pre2 = pre1 + PRE_FLOATS;
    float* pre3 = pre2 + PRE_FLOATS;
    float* preK = pre0 + ks * PRE_FLOATS;

    float gx4[4];
    {
        const float* gx = &g_gx2[(((size_t)0 * NBLK + bx) * kB + ub) * 32];
#pragma unroll
        for (int g = 0; g < 4; ++g) gx4[g] = gx[8 * g + uj];
    }

    auto stageA = [&](int c) {
        const int buf = c % 3;
        const uint32_t ahi = sb + OFF_A + buf * 2 * ABUF;
        const uint32_t alo = ahi + ABUF;
        const size_t g0 = (size_t)s_row0 * kH + c * 64 + s_c16 * 8;
        cp16(ahi + so0, &g_hhi[g0]);
        cp16(alo + so0, &g_hlo[g0]);
    };

    for (int t = 0; t < kT; ++t) {
        float C00[4] = {0,0,0,0}, C01[4] = {0,0,0,0};
        float C10[4] = {0,0,0,0}, C11[4] = {0,0,0,0};

        stageA(0); cp_commit();
        stageA(1); cp_commit();

        for (int c = 0; c < 16; ++c) {
            cp_wait1();
            __syncthreads();
            if (c + 2 < 16) stageA(c + 2);
            cp_commit();

            const int buf = c % 3;
            const uint32_t ahi = sb + OFF_A + buf * 2 * ABUF;
            const uint32_t alo = ahi + ABUF;
            uint32_t ah[4], al[4], bh0[4], bh1[4], bl0[4], bl1[4];
            ldsm_x4(ah, ahi + a_off);
            ldsm_x4(al, alo + a_off);
            const uint32_t bo = (uint32_t)(c * 128 + ks * 32);
            ldsm_x4(bh0, bHi[0] + bo);
            ldsm_x4(bh1, bHi[1] + bo);
            ldsm_x4(bl0, bLo[0] + bo);
            ldsm_x4(bl1, bLo[1] + bo);
            mma_bf16(C00, ah, bh0[0], bh0[1]); mma_bf16(C01, ah, bh0[2], bh0[3]);
            mma_bf16(C10, ah, bh1[0], bh1[1]); mma_bf16(C11, ah, bh1[2], bh1[3]);
            mma_bf16(C00, ah, bl0[0], bl0[1]); mma_bf16(C01, ah, bl0[2], bl0[3]);
            mma_bf16(C10, ah, bl1[0], bl1[1]); mma_bf16(C11, ah, bl1[2], bl1[3]);
            mma_bf16(C00, al, bh0[0], bh0[1]); mma_bf16(C01, al, bh0[2], bh0[3]);
            mma_bf16(C10, al, bh1[0], bh1[1]); mma_bf16(C11, al, bh1[2], bh1[3]);
        }

        // publish partials into pre[ks] (stride 34 -> float2 stores aligned)
        {
            const int r0 = 16 * mi + (lane >> 2);
            const int cb = (lane & 3) * 2;
            float2 v;
            v.x = C00[0]; v.y = C00[1];
            *reinterpret_cast<float2*>(&preK[r0 * PRE_STRIDE + cb]) = v;
            v.x = C00[2]; v.y = C00[3];
            *reinterpret_cast<float2*>(&preK[(r0 + 8) * PRE_STRIDE + cb]) = v;
            v.x = C01[0]; v.y = C01[1];
            *reinterpret_cast<float2*>(&preK[r0 * PRE_STRIDE + cb + 8]) = v;
            v.x = C01[2]; v.y = C01[3];
            *reinterpret_cast<float2*>(&preK[(r0 + 8) * PRE_STRIDE + cb + 8]) = v;
            v.x = C10[0]; v.y = C10[1];
            *reinterpret_cast<float2*>(&preK[r0 * PRE_STRIDE + cb + 16]) = v;
            v.x = C10[2]; v.y = C10[3];
            *reinterpret_cast<float2*>(&preK[(r0 + 8) * PRE_STRIDE + cb + 16]) = v;
            v.x = C11[0]; v.y = C11[1];
            *reinterpret_cast<float2*>(&preK[r0 * PRE_STRIDE + cb + 24]) = v;
            v.x = C11[2]; v.y = C11[3];
            *reinterpret_cast<float2*>(&preK[(r0 + 8) * PRE_STRIDE + cb + 24]) = v;
        }
        __syncthreads();

        // gate math + c/h update (1 item/thread)
        {
            const int b = ub, j = uj;
            const int o0 = b * PRE_STRIDE + j;
            float pf = pre0[o0]      + pre1[o0]      + pre2[o0]      + pre3[o0]      + gx4[0];
            float pi = pre0[o0 + 8]  + pre1[o0 + 8]  + pre2[o0 + 8]  + pre3[o0 + 8]  + gx4[1];
            float pg = pre0[o0 + 16] + pre1[o0 + 16] + pre2[o0 + 16] + pre3[o0 + 16] + gx4[2];
            float po = pre0[o0 + 24] + pre1[o0 + 24] + pre2[o0 + 24] + pre3[o0 + 24] + gx4[3];
            float f  = sigmoidf_(pf);
            float ii = sigmoidf_(pi);
            float gg = tanhf(pg);
            float oo = sigmoidf_(po);
            float cn = f * c_s[tid] + ii * gg;
            c_s[tid] = cn;
            float h = oo * tanhf(cn);
            out[(size_t)t * kBH + (size_t)b * kH + n0h + j] = h;
            __nv_bfloat16 bh16, bl16;
            split_bf16(h, bh16, bl16);
            g_hhi[b * kH + n0h + j] = bh16;
            g_hlo[b * kH + n0h + j] = bl16;
            if (t == kT - 1) {
                out[(size_t)kT * kBH + (size_t)b * kH + n0h + j] = h;
                out[(size_t)kT * kBH + kBH + (size_t)b * kH + n0h + j] = cn;
            }
        }

        // split global barrier
        if (t < kT - 1) {
            __syncthreads();
            if (tid == 0) bar_arrive_release(&g_bar);
            {
                const float* gx = &g_gx2[(((size_t)(t + 1) * NBLK + bx) * kB + ub) * 32];
#pragma unroll
                for (int g = 0; g < 4; ++g) gx4[g] = gx[8 * g + uj];
            }
            if (tid == 0) {
                const unsigned tgt = (unsigned)(t + 2) * NBLK;
                while (ld_acquire(&g_bar) < tgt) { __nanosleep(16); }
            }
            __syncthreads();
        }
    }
}

// ---------------------------------------------------------------------------
extern "C" void kernel_launch(void* const* d_in, const int* in_sizes, int n_in,
                              void* d_out, int out_size)
{
    const float* x  = (const float*)d_in[0];
    const float* Wf = (const float*)d_in[1];
    const float* bf = (const float*)d_in[2];
    const float* Wi = (const float*)d_in[3];
    const float* bi = (const float*)d_in[4];
    const float* Wc = (const float*)d_in[5];
    const float* bc = (const float*)d_in[6];
    const float* Wo = (const float*)d_in[7];
    const float* bo = (const float*)d_in[8];
    float* out = (float*)d_out;

    cudaFuncSetAttribute(phase1_hmma,
                         cudaFuncAttributeMaxDynamicSharedMemorySize, P1_SM);
    cudaFuncSetAttribute(lstm_hmma3,
                         cudaFuncAttributeMaxDynamicSharedMemorySize, SM_TOTAL2);

    reset_kernel<<<1, 1>>>();
    prep_x<<<(kT * kB * kIN) / 256, 256>>>(x);
    prep_wx<<<(4096 * kIN) / 256, 256>>>(Wf, Wi, Wc, Wo);
    prep_weights<<<NBLK, 256>>>(Wf, Wi, Wc, Wo);

    dim3 g1(4096 / 128, (kT * kB) / 128);   // 32 x 256
    phase1_hmma<<<g1, 512, P1_SM>>>(bf, bi, bc, bo);

    lstm_hmma3<<<NBLK, 512, SM_TOTAL2>>>(out);
}